// round 6
// baseline (speedup 1.0000x reference)
#include <cuda_runtime.h>
#include <cuda_bf16.h>
#include <math.h>

#define NT 8192
#define CD 128
#define NCLUS 256
#define SQRT_C 11.313708498984761f
#define FLTMAX 3.402823466e38f

// GEMM tile config
#define BF_PITCH 136                       // bf16 elems per smem row (272B)
#define BF_TILE (128 * BF_PITCH * 2)       // 34816 B per bf16 tile
#define F32_PITCH 132
#define F32_TILE (128 * F32_PITCH * 4)     // 67584 B
#define SMEM_NEED (6 * BF_TILE)            // 208896 B (f32 tiles reuse this)

// ---------------- scratch (static device globals; no allocs) ----------------
__device__ float g_D2[(long long)NT * NT];
__device__ float g_sq[NT];
__device__ float g_density[NT];
__device__ float g_score[NT];
__device__ unsigned int g_maxbits;
__device__ __nv_bfloat16 g_X0[NT * CD];
__device__ __nv_bfloat16 g_X1[NT * CD];
__device__ __nv_bfloat16 g_X2[NT * CD];

// ---------------- jax threefry2x32 noise, bit-exact ----------------
__device__ __forceinline__ unsigned int rotl(unsigned int x, int d) {
    return (x << d) | (x >> (32 - d));
}

__device__ float jax_noise(int i) {
    unsigned int x0, x1;
    if (i < 4096) { x0 = (unsigned int)i;          x1 = (unsigned int)(i + 4096); }
    else          { x0 = (unsigned int)(i - 4096); x1 = (unsigned int)i; }
    const unsigned int ks0 = 0u, ks1 = 1u, ks2 = 0u ^ 1u ^ 0x1BD11BDAu;
    x0 += ks0; x1 += ks1;
#define TFR(r) { x0 += x1; x1 = rotl(x1, r); x1 ^= x0; }
    TFR(13) TFR(15) TFR(26) TFR(6)
    x0 += ks1; x1 += ks2 + 1u;
    TFR(17) TFR(29) TFR(16) TFR(24)
    x0 += ks2; x1 += ks0 + 2u;
    TFR(13) TFR(15) TFR(26) TFR(6)
    x0 += ks0; x1 += ks1 + 3u;
    TFR(17) TFR(29) TFR(16) TFR(24)
    x0 += ks1; x1 += ks2 + 4u;
    TFR(13) TFR(15) TFR(26) TFR(6)
    x0 += ks2; x1 += ks0 + 5u;
#undef TFR
    unsigned int bits = (i < 4096) ? x0 : x1;
    unsigned int fb = (bits >> 9) | 0x3f800000u;
    return __uint_as_float(fb) - 1.0f;
}

// ---------------- mma/ldmatrix helpers (portable PTX, sm_80+) ----------------
__device__ __forceinline__ unsigned int smem_u32(const void* p) {
    unsigned int a;
    asm("{ .reg .u64 t; cvta.to.shared.u64 t, %1; cvt.u32.u64 %0, t; }" : "=r"(a) : "l"(p));
    return a;
}
__device__ __forceinline__ void ldsm4(unsigned int* r, unsigned int addr) {
    asm volatile("ldmatrix.sync.aligned.m8n8.x4.shared.b16 {%0,%1,%2,%3}, [%4];"
                 : "=r"(r[0]), "=r"(r[1]), "=r"(r[2]), "=r"(r[3]) : "r"(addr));
}
__device__ __forceinline__ void mma16816(float* c,
                                         unsigned int a0, unsigned int a1,
                                         unsigned int a2, unsigned int a3,
                                         unsigned int b0, unsigned int b1) {
    asm volatile(
        "mma.sync.aligned.m16n8k16.row.col.f32.bf16.bf16.f32 "
        "{%0,%1,%2,%3}, {%4,%5,%6,%7}, {%8,%9}, {%0,%1,%2,%3};"
        : "+f"(c[0]), "+f"(c[1]), "+f"(c[2]), "+f"(c[3])
        : "r"(a0), "r"(a1), "r"(a2), "r"(a3), "r"(b0), "r"(b1));
}

// ---------------- kernel 1: row sum-of-squares + reset global max ----------------
__global__ void k_rownorm(const float* __restrict__ X) {
    if (blockIdx.x == 0 && threadIdx.x == 0) g_maxbits = 0u;
    int row = blockIdx.x * 8 + (threadIdx.x >> 5);
    int lane = threadIdx.x & 31;
    const float4 v = reinterpret_cast<const float4*>(X)[(long long)row * 32 + lane];
    float s = __fmul_rn(v.x, v.x);
    s = __fadd_rn(s, __fmul_rn(v.y, v.y));
    s = __fadd_rn(s, __fmul_rn(v.z, v.z));
    s = __fadd_rn(s, __fmul_rn(v.w, v.w));
    #pragma unroll
    for (int off = 16; off > 0; off >>= 1)
        s = __fadd_rn(s, __shfl_xor_sync(0xFFFFFFFFu, s, off));
    if (lane == 0) g_sq[row] = s;
}

// ---------------- kernel 1b: fp32 -> 3x bf16 limbs ----------------
__global__ void k_split(const float* __restrict__ X) {
    int i4 = blockIdx.x * 256 + threadIdx.x;
    float4 v = reinterpret_cast<const float4*>(X)[i4];
    float xs[4] = {v.x, v.y, v.z, v.w};
    unsigned short h0[4], h1[4], h2[4];
    #pragma unroll
    for (int q = 0; q < 4; q++) {
        float x = xs[q];
        __nv_bfloat16 b0 = __float2bfloat16(x);
        float r1 = __fadd_rn(x, -__bfloat162float(b0));
        __nv_bfloat16 b1 = __float2bfloat16(r1);
        float r2 = __fadd_rn(r1, -__bfloat162float(b1));
        __nv_bfloat16 b2 = __float2bfloat16(r2);
        h0[q] = __bfloat16_as_ushort(b0);
        h1[q] = __bfloat16_as_ushort(b1);
        h2[q] = __bfloat16_as_ushort(b2);
    }
    reinterpret_cast<ushort4*>(g_X0)[i4] = make_ushort4(h0[0], h0[1], h0[2], h0[3]);
    reinterpret_cast<ushort4*>(g_X1)[i4] = make_ushort4(h1[0], h1[1], h1[2], h1[3]);
    reinterpret_cast<ushort4*>(g_X2)[i4] = make_ushort4(h2[0], h2[1], h2[2], h2[3]);
}

// ---------------- kernel 2: mma.sync bf16x6 GEMM -> D2 ----------------
__global__ void __launch_bounds__(256, 1) k_mma() {
    extern __shared__ __align__(16) char dsm[];
    const unsigned int sbase = smem_u32(dsm);

    // triangle decode
    int rem = blockIdx.x;
    int bi = 0, span = 64;
    while (rem >= span) { rem -= span; span--; bi++; }
    int bj = bi + rem;
    const bool diag = (bi == bj);
    const int rows = bi * 128, cols = bj * 128;

    const int tid = threadIdx.x;
    const int wid = tid >> 5;
    const int lane = tid & 31;
    const int wm = wid >> 2;    // 0..1
    const int wn = wid & 3;     // 0..3

    // ---- fill 6 bf16 smem tiles (A limbs 0-2, B limbs 0-2), pitch 136 ----
    {
        const int r = tid >> 1, h = tid & 1;
        const __nv_bfloat16* srcs[3] = {g_X0, g_X1, g_X2};
        #pragma unroll
        for (int s = 0; s < 3; s++) {
            const uint4* srcA = reinterpret_cast<const uint4*>(
                srcs[s] + (long long)(rows + r) * CD + h * 64);
            uint4* dstA = reinterpret_cast<uint4*>(
                dsm + s * BF_TILE + (r * BF_PITCH + h * 64) * 2);
            const uint4* srcB = reinterpret_cast<const uint4*>(
                srcs[s] + (long long)(cols + r) * CD + h * 64);
            uint4* dstB = reinterpret_cast<uint4*>(
                dsm + (3 + s) * BF_TILE + (r * BF_PITCH + h * 64) * 2);
            #pragma unroll
            for (int c = 0; c < 8; c++) { dstA[c] = srcA[c]; dstB[c] = srcB[c]; }
        }
    }
    __syncthreads();

    // ---- mainloop: 6 limb passes x 8 k-steps, warp tile 64x32 ----
    float acc[4][4][4];
    #pragma unroll
    for (int mi = 0; mi < 4; mi++)
        #pragma unroll
        for (int ni = 0; ni < 4; ni++)
            #pragma unroll
            for (int q = 0; q < 4; q++) acc[mi][ni][q] = 0.0f;

    // ldmatrix per-lane address components (element units within tile)
    const int a_elem = (wm * 64 + (lane & 15)) * BF_PITCH + ((lane >> 4) << 3);
    const int b_elem = (wn * 32 + ((lane >> 4) << 3) + (lane & 7)) * BF_PITCH
                       + (((lane >> 3) & 1) << 3);

    const int TA[6] = {0, 0, 1, 1, 0, 2};
    const int TB[6] = {0, 1, 0, 1, 2, 0};

    #pragma unroll
    for (int p = 0; p < 6; p++) {
        const unsigned int aBase = sbase + TA[p] * BF_TILE + a_elem * 2;
        const unsigned int bBase = sbase + (3 + TB[p]) * BF_TILE + b_elem * 2;
        #pragma unroll
        for (int ks = 0; ks < 8; ks++) {
            const unsigned int kOff = (unsigned int)(ks * 16) * 2;
            unsigned int ra[4][4], rb[2][4];
            #pragma unroll
            for (int mi = 0; mi < 4; mi++)
                ldsm4(ra[mi], aBase + (unsigned int)(mi * 16 * BF_PITCH) * 2 + kOff);
            #pragma unroll
            for (int nh = 0; nh < 2; nh++)
                ldsm4(rb[nh], bBase + (unsigned int)(nh * 16 * BF_PITCH) * 2 + kOff);
            #pragma unroll
            for (int mi = 0; mi < 4; mi++)
                #pragma unroll
                for (int ni = 0; ni < 4; ni++)
                    mma16816(acc[mi][ni],
                             ra[mi][0], ra[mi][1], ra[mi][2], ra[mi][3],
                             rb[ni >> 1][(ni & 1) * 2], rb[ni >> 1][(ni & 1) * 2 + 1]);
        }
    }
    __syncthreads();   // bf16 tiles dead; reuse smem for f32 epilogue tiles

    // ---- STS accs to f32 tile (+ transposed copy for mirror) ----
    float* fN = reinterpret_cast<float*>(dsm);
    float* fT = reinterpret_cast<float*>(dsm + F32_TILE);
    {
        const int g = lane >> 2, c2 = (lane & 3) * 2;
        #pragma unroll
        for (int mi = 0; mi < 4; mi++) {
            const int m0 = wm * 64 + mi * 16 + g;
            #pragma unroll
            for (int ni = 0; ni < 4; ni++) {
                const int n0 = wn * 32 + ni * 8 + c2;
                float* a = acc[mi][ni];
                *reinterpret_cast<float2*>(&fN[m0 * F32_PITCH + n0]) =
                    make_float2(a[0], a[1]);
                *reinterpret_cast<float2*>(&fN[(m0 + 8) * F32_PITCH + n0]) =
                    make_float2(a[2], a[3]);
                if (!diag) {
                    fT[n0 * F32_PITCH + m0]           = a[0];
                    fT[(n0 + 1) * F32_PITCH + m0]     = a[1];
                    fT[n0 * F32_PITCH + m0 + 8]       = a[2];
                    fT[(n0 + 1) * F32_PITCH + m0 + 8] = a[3];
                }
            }
        }
    }
    __syncthreads();

    // ---- coalesced stores: warp w handles 16 rows (and 16 mirror cols) ----
    #pragma unroll
    for (int rr = 0; rr < 16; rr++) {
        const int r = wid * 16 + rr;
        const int ig = rows + r;
        const float sr = g_sq[ig];
        float4 a = *reinterpret_cast<float4*>(&fN[r * F32_PITCH + lane * 4]);
        const float4 sc = *reinterpret_cast<const float4*>(&g_sq[cols + lane * 4]);
        float4 v;
        v.x = __fadd_rn(__fadd_rn(sr, sc.x), -2.0f * a.x);
        v.y = __fadd_rn(__fadd_rn(sr, sc.y), -2.0f * a.y);
        v.z = __fadd_rn(__fadd_rn(sr, sc.z), -2.0f * a.z);
        v.w = __fadd_rn(__fadd_rn(sr, sc.w), -2.0f * a.w);
        *reinterpret_cast<float4*>(&g_D2[(long long)ig * NT + cols + lane * 4]) = v;
    }
    if (!diag) {
        #pragma unroll
        for (int rr = 0; rr < 16; rr++) {
            const int j = wid * 16 + rr;
            const int jg = cols + j;
            const float sj = g_sq[jg];
            float4 a = *reinterpret_cast<float4*>(&fT[j * F32_PITCH + lane * 4]);
            const float4 si = *reinterpret_cast<const float4*>(&g_sq[rows + lane * 4]);
            float4 v;
            v.x = __fadd_rn(__fadd_rn(si.x, sj), -2.0f * a.x);
            v.y = __fadd_rn(__fadd_rn(si.y, sj), -2.0f * a.y);
            v.z = __fadd_rn(__fadd_rn(si.z, sj), -2.0f * a.z);
            v.w = __fadd_rn(__fadd_rn(si.w, sj), -2.0f * a.w);
            *reinterpret_cast<float4*>(&g_D2[(long long)jg * NT + rows + lane * 4]) = v;
        }
    }
}

// ---------------- kernel 3 (pass A): 5-NN density + global max d2 ----------------
__global__ void __launch_bounds__(256) k_knn() {
    const int i = blockIdx.x;
    const int t = threadIdx.x;
    const float4* __restrict__ row4 =
        reinterpret_cast<const float4*>(g_D2 + (long long)i * NT);

    float s0 = FLTMAX, s1 = FLTMAX, s2 = FLTMAX, s3 = FLTMAX, s4 = FLTMAX;
    float vmax = -FLTMAX;

    #define INSERT(x)                                                        \
        if (x < s4) {                                                        \
            if (x < s3) { s4 = s3;                                           \
                if (x < s2) { s3 = s2;                                       \
                    if (x < s1) { s2 = s1;                                   \
                        if (x < s0) { s1 = s0; s0 = x; } else s1 = x;        \
                    } else s2 = x;                                           \
                } else s3 = x;                                               \
            } else s4 = x;                                                   \
        }

    for (int j = t; j < NT / 4; j += 256) {
        float4 rr = row4[j];
        vmax = fmaxf(fmaxf(fmaxf(vmax, rr.x), fmaxf(rr.y, rr.z)), rr.w);
        INSERT(rr.x) INSERT(rr.y) INSERT(rr.z) INSERT(rr.w)
    }
    #undef INSERT

    __shared__ float sh[256 * 5];
    __shared__ float shm[256];
    sh[t * 5 + 0] = s0; sh[t * 5 + 1] = s1; sh[t * 5 + 2] = s2;
    sh[t * 5 + 3] = s3; sh[t * 5 + 4] = s4;
    shm[t] = vmax;
    __syncthreads();

    for (int stride = 128; stride >= 1; stride >>= 1) {
        if (t < stride) {
            float* A = &sh[t * 5];
            float* B = &sh[(t + stride) * 5];
            float o[5];
            int ia = 0, ib = 0;
            #pragma unroll
            for (int q = 0; q < 5; q++) {
                float av = (ia < 5) ? A[ia] : FLTMAX;
                float bv = (ib < 5) ? B[ib] : FLTMAX;
                if (av <= bv) { o[q] = av; ia++; } else { o[q] = bv; ib++; }
            }
            #pragma unroll
            for (int q = 0; q < 5; q++) A[q] = o[q];
            shm[t] = fmaxf(shm[t], shm[t + stride]);
        }
        __syncthreads();
    }

    if (t == 0) {
        atomicMax(&g_maxbits, __float_as_uint(fmaxf(shm[0], 0.0f)));
        float accv = 0.0f;
        #pragma unroll
        for (int q = 0; q < 5; q++) {
            float d = __fdiv_rn(__fsqrt_rn(fmaxf(sh[q], 0.0f)), SQRT_C);
            accv = __fadd_rn(accv, __fmul_rn(d, d));
        }
        float mean = __fdiv_rn(accv, 5.0f);
        float dens = (float)exp(-(double)mean);
        dens = __fadd_rn(dens, __fmul_rn(jax_noise(i), 1e-6f));
        g_density[i] = dens;
    }
}

// ---------------- kernel 4 (pass B): dist_parent + score ----------------
__global__ void __launch_bounds__(256) k_parent() {
    const int i = blockIdx.x;
    const int t = threadIdx.x;
    const float di = g_density[i];
    const float4* __restrict__ row4 =
        reinterpret_cast<const float4*>(g_D2 + (long long)i * NT);
    const float4* __restrict__ den4 =
        reinterpret_cast<const float4*>(g_density);

    float lmin = FLTMAX;
    for (int j = t; j < NT / 4; j += 256) {
        float4 rr = row4[j];
        float4 d = den4[j];
        float c0 = (d.x > di) ? fmaxf(rr.x, 0.0f) : FLTMAX;
        float c1 = (d.y > di) ? fmaxf(rr.y, 0.0f) : FLTMAX;
        float c2 = (d.z > di) ? fmaxf(rr.z, 0.0f) : FLTMAX;
        float c3 = (d.w > di) ? fmaxf(rr.w, 0.0f) : FLTMAX;
        lmin = fminf(lmin, fminf(fminf(c0, c1), fminf(c2, c3)));
    }

    __shared__ float sm[256];
    sm[t] = lmin;
    __syncthreads();
    for (int stride = 128; stride >= 1; stride >>= 1) {
        if (t < stride) sm[t] = fminf(sm[t], sm[t + stride]);
        __syncthreads();
    }

    if (t == 0) {
        float m = sm[0];
        float dp;
        if (m >= FLTMAX) {
            float mx = __uint_as_float(g_maxbits);
            dp = __fdiv_rn(__fsqrt_rn(mx), SQRT_C);
        } else {
            dp = __fdiv_rn(__fsqrt_rn(m), SQRT_C);
        }
        g_score[i] = __fmul_rn(dp, di);
    }
}

// ---------------- kernel 5: exact top-256 ----------------
__global__ void k_topk(float* __restrict__ out) {
    extern __shared__ char dyn[];
    float* ss = reinterpret_cast<float*>(dyn);
    unsigned short* si = reinterpret_cast<unsigned short*>(dyn + NT * 4);
    const int t = threadIdx.x;

    for (int i = t; i < NT; i += 1024) {
        ss[i] = g_score[i];
        si[i] = (unsigned short)i;
    }
    __syncthreads();

    for (int k = 2; k <= NT; k <<= 1) {
        for (int j = k >> 1; j > 0; j >>= 1) {
            for (int i = t; i < NT; i += 1024) {
                int ixj = i ^ j;
                if (ixj > i) {
                    unsigned short ia = si[i], ib = si[ixj];
                    unsigned long long ka =
                        ((unsigned long long)__float_as_uint(ss[ia]) << 32) |
                        (unsigned int)(NT - 1 - (int)ia);
                    unsigned long long kb =
                        ((unsigned long long)__float_as_uint(ss[ib]) << 32) |
                        (unsigned int)(NT - 1 - (int)ib);
                    bool desc = ((i & k) == 0);
                    if (desc ? (ka < kb) : (ka > kb)) { si[i] = ib; si[ixj] = ia; }
                }
            }
            __syncthreads();
        }
    }

    if (t < NCLUS) out[t] = (float)si[t];
}

// ---------------- launch ----------------
extern "C" void kernel_launch(void* const* d_in, const int* in_sizes, int n_in,
                              void* d_out, int out_size) {
    const float* X = (const float*)d_in[0];
    float* out = (float*)d_out;

    cudaFuncSetAttribute(k_mma, cudaFuncAttributeMaxDynamicSharedMemorySize, SMEM_NEED);

    k_rownorm<<<NT / 8, 256>>>(X);
    k_split<<<(NT * CD / 4) / 256, 256>>>(X);
    k_mma<<<(64 * 65) / 2, 256, SMEM_NEED>>>();
    k_knn<<<NT, 256>>>();
    k_parent<<<NT, 256>>>();
    k_topk<<<1, 1024, 48 * 1024>>>(out);
}

// round 7
// speedup vs baseline: 1.1366x; 1.1366x over previous
#include <cuda_runtime.h>
#include <math.h>

#define NT 8192
#define CD 128
#define NCLUS 256
#define SQRT_C 11.313708498984761f
#define FLTMAX 3.402823466e38f

// ---------------- scratch (static device globals; no allocs) ----------------
__device__ float g_D2[(long long)NT * NT];   // 256 MB squared-distance matrix
__device__ float g_sq[NT];
__device__ float g_density[NT];
__device__ float g_score[NT];

// ---------------- jax threefry2x32 noise, bit-exact ----------------
__device__ __forceinline__ unsigned int rotl(unsigned int x, int d) {
    return (x << d) | (x >> (32 - d));
}

__device__ float jax_noise(int i) {
    unsigned int x0, x1;
    if (i < 4096) { x0 = (unsigned int)i;          x1 = (unsigned int)(i + 4096); }
    else          { x0 = (unsigned int)(i - 4096); x1 = (unsigned int)i; }
    const unsigned int ks0 = 0u, ks1 = 1u, ks2 = 0u ^ 1u ^ 0x1BD11BDAu;
    x0 += ks0; x1 += ks1;
#define TFR(r) { x0 += x1; x1 = rotl(x1, r); x1 ^= x0; }
    TFR(13) TFR(15) TFR(26) TFR(6)
    x0 += ks1; x1 += ks2 + 1u;
    TFR(17) TFR(29) TFR(16) TFR(24)
    x0 += ks2; x1 += ks0 + 2u;
    TFR(13) TFR(15) TFR(26) TFR(6)
    x0 += ks0; x1 += ks1 + 3u;
    TFR(17) TFR(29) TFR(16) TFR(24)
    x0 += ks1; x1 += ks2 + 4u;
    TFR(13) TFR(15) TFR(26) TFR(6)
    x0 += ks2; x1 += ks0 + 5u;
#undef TFR
    unsigned int bits = (i < 4096) ? x0 : x1;
    unsigned int fb = (bits >> 9) | 0x3f800000u;
    return __uint_as_float(fb) - 1.0f;   // uniform [0,1), exactly jax's mapping
}

// ---------------- kernel 1: row sum-of-squares ----------------
__global__ void k_rownorm(const float* __restrict__ X) {
    int row = blockIdx.x * 8 + (threadIdx.x >> 5);
    int lane = threadIdx.x & 31;
    const float4 v = reinterpret_cast<const float4*>(X)[(long long)row * 32 + lane];
    float s = __fmul_rn(v.x, v.x);
    s = __fadd_rn(s, __fmul_rn(v.y, v.y));
    s = __fadd_rn(s, __fmul_rn(v.z, v.z));
    s = __fadd_rn(s, __fmul_rn(v.w, v.w));
    #pragma unroll
    for (int off = 16; off > 0; off >>= 1)
        s = __fadd_rn(s, __shfl_xor_sync(0xFFFFFFFFu, s, off));
    if (lane == 0) g_sq[row] = s;
}

// ---------------- kernel 2: symmetric SGEMM -> D2 (plain FFMA, R3 design) ---------
__global__ void __launch_bounds__(256) k_gemm(const float* __restrict__ X) {
    __shared__ float As[8][128];
    __shared__ float Bs[8][128];

    int rem = blockIdx.x;
    int bi = 0, span = 64;
    while (rem >= span) { rem -= span; span--; bi++; }
    int bj = bi + rem;

    const int rows = bi * 128, cols = bj * 128;
    const int tid = threadIdx.x;
    const int tx = tid & 15, ty = tid >> 4;

    float acc[8][8];
    #pragma unroll
    for (int m = 0; m < 8; m++)
        #pragma unroll
        for (int n = 0; n < 8; n++) acc[m][n] = 0.0f;

    const int lrow = tid >> 1;
    const int lk = (tid & 1) * 4;

    for (int k0 = 0; k0 < CD; k0 += 8) {
        float4 va = *reinterpret_cast<const float4*>(X + (long long)(rows + lrow) * CD + k0 + lk);
        float4 vb = *reinterpret_cast<const float4*>(X + (long long)(cols + lrow) * CD + k0 + lk);
        __syncthreads();
        As[lk + 0][lrow] = va.x; As[lk + 1][lrow] = va.y;
        As[lk + 2][lrow] = va.z; As[lk + 3][lrow] = va.w;
        Bs[lk + 0][lrow] = vb.x; Bs[lk + 1][lrow] = vb.y;
        Bs[lk + 2][lrow] = vb.z; Bs[lk + 3][lrow] = vb.w;
        __syncthreads();

        #pragma unroll
        for (int kk = 0; kk < 8; kk++) {
            float4 a0 = *reinterpret_cast<float4*>(&As[kk][ty * 8]);
            float4 a1 = *reinterpret_cast<float4*>(&As[kk][ty * 8 + 4]);
            float4 b0 = *reinterpret_cast<float4*>(&Bs[kk][tx * 8]);
            float4 b1 = *reinterpret_cast<float4*>(&Bs[kk][tx * 8 + 4]);
            float am[8] = {a0.x, a0.y, a0.z, a0.w, a1.x, a1.y, a1.z, a1.w};
            float bn[8] = {b0.x, b0.y, b0.z, b0.w, b1.x, b1.y, b1.z, b1.w};
            #pragma unroll
            for (int m = 0; m < 8; m++)
                #pragma unroll
                for (int n = 0; n < 8; n++)
                    acc[m][n] = __fmaf_rn(am[m], bn[n], acc[m][n]);
        }
    }

    float sr[8], sc[8];
    #pragma unroll
    for (int m = 0; m < 8; m++) sr[m] = g_sq[rows + ty * 8 + m];
    #pragma unroll
    for (int n = 0; n < 8; n++) sc[n] = g_sq[cols + tx * 8 + n];

    float v[8][8];
    #pragma unroll
    for (int m = 0; m < 8; m++)
        #pragma unroll
        for (int n = 0; n < 8; n++)
            v[m][n] = __fadd_rn(__fadd_rn(sr[m], sc[n]), -2.0f * acc[m][n]);

    #pragma unroll
    for (int m = 0; m < 8; m++) {
        long long base = (long long)(rows + ty * 8 + m) * NT + cols + tx * 8;
        *reinterpret_cast<float4*>(g_D2 + base)     = make_float4(v[m][0], v[m][1], v[m][2], v[m][3]);
        *reinterpret_cast<float4*>(g_D2 + base + 4) = make_float4(v[m][4], v[m][5], v[m][6], v[m][7]);
    }
    if (bi != bj) {
        #pragma unroll
        for (int n = 0; n < 8; n++) {
            long long base = (long long)(cols + tx * 8 + n) * NT + rows + ty * 8;
            *reinterpret_cast<float4*>(g_D2 + base)     = make_float4(v[0][n], v[1][n], v[2][n], v[3][n]);
            *reinterpret_cast<float4*>(g_D2 + base + 4) = make_float4(v[4][n], v[5][n], v[6][n], v[7][n]);
        }
    }
}

// ---------------- kernel 3 (pass A): 5-NN density (fast-path compare) -------------
__global__ void __launch_bounds__(256) k_knn() {
    const int i = blockIdx.x;
    const int t = threadIdx.x;
    const float4* __restrict__ row4 =
        reinterpret_cast<const float4*>(g_D2 + (long long)i * NT);

    float s0 = FLTMAX, s1 = FLTMAX, s2 = FLTMAX, s3 = FLTMAX, s4 = FLTMAX;

    #define INSERT(x)                                                        \
        if (x < s4) {                                                        \
            if (x < s3) { s4 = s3;                                           \
                if (x < s2) { s3 = s2;                                       \
                    if (x < s1) { s2 = s1;                                   \
                        if (x < s0) { s1 = s0; s0 = x; } else s1 = x;        \
                    } else s2 = x;                                           \
                } else s3 = x;                                               \
            } else s4 = x;                                                   \
        }

    for (int j = t; j < NT / 4; j += 256) {
        float4 rr = row4[j];
        float m01 = fminf(rr.x, rr.y);
        float m23 = fminf(rr.z, rr.w);
        if (fminf(m01, m23) < s4) {       // rare hit: full insert
            INSERT(rr.x) INSERT(rr.y) INSERT(rr.z) INSERT(rr.w)
        }
    }
    #undef INSERT

    __shared__ float sh[256 * 5];
    sh[t * 5 + 0] = s0; sh[t * 5 + 1] = s1; sh[t * 5 + 2] = s2;
    sh[t * 5 + 3] = s3; sh[t * 5 + 4] = s4;
    __syncthreads();

    for (int stride = 128; stride >= 1; stride >>= 1) {
        if (t < stride) {
            float* A = &sh[t * 5];
            float* B = &sh[(t + stride) * 5];
            float o[5];
            int ia = 0, ib = 0;
            #pragma unroll
            for (int q = 0; q < 5; q++) {
                float av = (ia < 5) ? A[ia] : FLTMAX;
                float bv = (ib < 5) ? B[ib] : FLTMAX;
                if (av <= bv) { o[q] = av; ia++; } else { o[q] = bv; ib++; }
            }
            #pragma unroll
            for (int q = 0; q < 5; q++) A[q] = o[q];
        }
        __syncthreads();
    }

    if (t == 0) {
        float accv = 0.0f;
        #pragma unroll
        for (int q = 0; q < 5; q++) {
            float d = __fdiv_rn(__fsqrt_rn(fmaxf(sh[q], 0.0f)), SQRT_C);
            accv = __fadd_rn(accv, __fmul_rn(d, d));
        }
        float mean = __fdiv_rn(accv, 5.0f);
        float dens = (float)exp(-(double)mean);
        dens = __fadd_rn(dens, __fmul_rn(jax_noise(i), 1e-6f));
        g_density[i] = dens;
    }
}

// ---------------- kernel 4 (pass B): dist_parent + score -------------------------
// Point with no higher-density neighbor (exactly the density argmax) gets
// score = FLT_MAX: rank-equivalent to dist_max*density (strict global max).
__global__ void __launch_bounds__(256) k_parent() {
    const int i = blockIdx.x;
    const int t = threadIdx.x;
    const float di = g_density[i];
    const float4* __restrict__ row4 =
        reinterpret_cast<const float4*>(g_D2 + (long long)i * NT);
    const float4* __restrict__ den4 =
        reinterpret_cast<const float4*>(g_density);

    float l0 = FLTMAX, l1 = FLTMAX, l2 = FLTMAX, l3 = FLTMAX;
    for (int j = t; j < NT / 4; j += 256) {
        float4 rr = row4[j];
        float4 d = den4[j];
        l0 = fminf(l0, (d.x > di) ? rr.x : FLTMAX);
        l1 = fminf(l1, (d.y > di) ? rr.y : FLTMAX);
        l2 = fminf(l2, (d.z > di) ? rr.z : FLTMAX);
        l3 = fminf(l3, (d.w > di) ? rr.w : FLTMAX);
    }
    float lmin = fminf(fminf(l0, l1), fminf(l2, l3));

    __shared__ float sm[256];
    sm[t] = lmin;
    __syncthreads();
    for (int stride = 128; stride >= 1; stride >>= 1) {
        if (t < stride) sm[t] = fminf(sm[t], sm[t + stride]);
        __syncthreads();
    }

    if (t == 0) {
        float m = sm[0];
        if (m >= FLTMAX) {
            g_score[i] = FLTMAX;   // density argmax: strict top-1 either way
        } else {
            float dp = __fdiv_rn(__fsqrt_rn(fmaxf(m, 0.0f)), SQRT_C);
            g_score[i] = __fmul_rn(dp, di);
        }
    }
}

// ---------------- kernel 5: exact top-256 (descending, lower-index-first ties) ----
__global__ void k_topk(float* __restrict__ out) {
    extern __shared__ char dyn[];
    float* ss = reinterpret_cast<float*>(dyn);                            // 32KB
    unsigned short* si = reinterpret_cast<unsigned short*>(dyn + NT * 4); // 16KB
    const int t = threadIdx.x;  // 1024 threads

    for (int i = t; i < NT; i += 1024) {
        ss[i] = g_score[i];
        si[i] = (unsigned short)i;
    }
    __syncthreads();

    for (int k = 2; k <= NT; k <<= 1) {
        for (int j = k >> 1; j > 0; j >>= 1) {
            for (int i = t; i < NT; i += 1024) {
                int ixj = i ^ j;
                if (ixj > i) {
                    unsigned short ia = si[i], ib = si[ixj];
                    unsigned long long ka =
                        ((unsigned long long)__float_as_uint(ss[ia]) << 32) |
                        (unsigned int)(NT - 1 - (int)ia);
                    unsigned long long kb =
                        ((unsigned long long)__float_as_uint(ss[ib]) << 32) |
                        (unsigned int)(NT - 1 - (int)ib);
                    bool desc = ((i & k) == 0);
                    if (desc ? (ka < kb) : (ka > kb)) { si[i] = ib; si[ixj] = ia; }
                }
            }
            __syncthreads();
        }
    }

    if (t < NCLUS) out[t] = (float)si[t];   // indices as float32
}

// ---------------- launch ----------------
extern "C" void kernel_launch(void* const* d_in, const int* in_sizes, int n_in,
                              void* d_out, int out_size) {
    const float* X = (const float*)d_in[0];
    float* out = (float*)d_out;

    k_rownorm<<<NT / 8, 256>>>(X);
    k_gemm<<<(64 * 65) / 2, 256>>>(X);
    k_knn<<<NT, 256>>>();
    k_parent<<<NT, 256>>>();
    k_topk<<<1, 1024, 48 * 1024>>>(out);
}